// round 13
// baseline (speedup 1.0000x reference)
#include <cuda_runtime.h>
#include <cuda_bf16.h>
#include <math.h>

// Problem constants
#define BDIM 64
#define TSTEPS 512
#define IDIM 512
#define HDIM 1024

#define NCTAS 128
#define NTHREADS 1024

typedef unsigned long long ull;

// ---------- packed f32x2 helpers ----------
__device__ __forceinline__ ull ffma2(ull a, ull b, ull c) {
    ull d;
    asm("fma.rn.f32x2 %0, %1, %2, %3;" : "=l"(d) : "l"(a), "l"(b), "l"(c));
    return d;
}
__device__ __forceinline__ float lo_f(ull v) {
    return __uint_as_float((unsigned)(v & 0xffffffffull));
}
__device__ __forceinline__ float hi_f(ull v) {
    return __uint_as_float((unsigned)(v >> 32));
}
__device__ __forceinline__ ull dup_f(float x) {
    unsigned u = __float_as_uint(x);
    return ((ull)u << 32) | u;
}
__device__ __forceinline__ unsigned ld_acq(const unsigned* p) {
    unsigned v;
    asm volatile("ld.acquire.gpu.global.u32 %0, [%1];" : "=r"(v) : "l"(p) : "memory");
    return v;
}
__device__ __forceinline__ void red_rel_add1(unsigned* p) {
    asm volatile("red.release.gpu.global.add.u32 [%0], 1;" :: "l"(p) : "memory");
}

// One flag per batch-group, each in its own 128B sector
__device__ unsigned g_flag[4 * 32];
#define FLAG_IDX(gb) ((gb) * 32)

// Contiguous fp32 ping-pong h-exchange buffer
__device__ __align__(16) float g_hx[2][BDIM][HDIM];

// init: h0 -> g_hx[0]; reset flags
__global__ void init_h0(const float* __restrict__ h0) {
    if (blockIdx.x == 0 && threadIdx.x < 4) g_flag[threadIdx.x * 32] = 0u;
    int idx = blockIdx.x * 256 + threadIdx.x;       // 16384 float4 slots
    float4 v = *(const float4*)(h0 + (size_t)idx * 4);
    int b = idx >> 8, g = idx & 255;
    *(float4*)(&g_hx[0][b][g * 4]) = v;
}

// ============================================================
// Kernel 1: xp = embeddings @ Wx^T + bx  -> written into hidden
// NT gemm, BM=128 BN=128 BK=16, 256 threads, 8x8/thread, FFMA2.
// DOUBLE-BUFFERED smem: prefetch tile k+1 to regs before computing
// tile k; one barrier per k-iteration (was two).
// ============================================================
#define GA_ULL (16 * 130)
#define GB_F   (16 * 132)
#define GSMEM_BYTES (2 * GA_ULL * 8 + 2 * GB_F * 4)

__global__ __launch_bounds__(256) void gemm_xproj(
    const float* __restrict__ A,
    const float* __restrict__ Bw,
    const float* __restrict__ bx,
    float* __restrict__ C)
{
    extern __shared__ char gsm[];
    ull*   Asb = (ull*)gsm;                       // [2][16][130] dup-packed
    float* Bsb = (float*)(gsm + 2 * GA_ULL * 8);  // [2][16][132]

    const int K = IDIM;
    const int N = HDIM;
    const int bm = blockIdx.y * 128;
    const int bn = blockIdx.x * 128;
    const int tid = threadIdx.x;
    const int tx = tid & 15;          // 8 cols
    const int ty = tid >> 4;          // 8 rows

    // tile-load jobs: job0 = tid, job1 = tid+256 (512 float4 per operand)
    const int r0 = tid >> 2,          q0 = tid & 3;
    const int r1 = (tid + 256) >> 2,  q1 = (tid + 256) & 3;

    ull acc[8][4];
    #pragma unroll
    for (int i = 0; i < 8; i++)
        #pragma unroll
        for (int j = 0; j < 4; j++) acc[i][j] = 0ull;

    // ---- prefetch + store tile 0 into buffer 0 ----
    {
        float4 pa0 = *(const float4*)(A  + (size_t)(bm + r0) * K + q0 * 4);
        float4 pa1 = *(const float4*)(A  + (size_t)(bm + r1) * K + q1 * 4);
        float4 pb0 = *(const float4*)(Bw + (size_t)(bn + r0) * K + q0 * 4);
        float4 pb1 = *(const float4*)(Bw + (size_t)(bn + r1) * K + q1 * 4);
        ull* As = Asb;
        float* Bs = Bsb;
        As[(q0 * 4 + 0) * 130 + r0] = dup_f(pa0.x);
        As[(q0 * 4 + 1) * 130 + r0] = dup_f(pa0.y);
        As[(q0 * 4 + 2) * 130 + r0] = dup_f(pa0.z);
        As[(q0 * 4 + 3) * 130 + r0] = dup_f(pa0.w);
        As[(q1 * 4 + 0) * 130 + r1] = dup_f(pa1.x);
        As[(q1 * 4 + 1) * 130 + r1] = dup_f(pa1.y);
        As[(q1 * 4 + 2) * 130 + r1] = dup_f(pa1.z);
        As[(q1 * 4 + 3) * 130 + r1] = dup_f(pa1.w);
        Bs[(q0 * 4 + 0) * 132 + r0] = pb0.x;
        Bs[(q0 * 4 + 1) * 132 + r0] = pb0.y;
        Bs[(q0 * 4 + 2) * 132 + r0] = pb0.z;
        Bs[(q0 * 4 + 3) * 132 + r0] = pb0.w;
        Bs[(q1 * 4 + 0) * 132 + r1] = pb1.x;
        Bs[(q1 * 4 + 1) * 132 + r1] = pb1.y;
        Bs[(q1 * 4 + 2) * 132 + r1] = pb1.z;
        Bs[(q1 * 4 + 3) * 132 + r1] = pb1.w;
    }
    __syncthreads();

    #pragma unroll 1
    for (int it = 0; it < 32; it++) {
        const int cur = it & 1;
        const ull* As = Asb + cur * GA_ULL;
        const float* Bs = Bsb + cur * GB_F;

        // prefetch tile it+1 (loads fly under the compute below)
        float4 na0, na1, nb0, nb1;
        if (it < 31) {
            const int kt = (it + 1) * 16;
            na0 = *(const float4*)(A  + (size_t)(bm + r0) * K + kt + q0 * 4);
            na1 = *(const float4*)(A  + (size_t)(bm + r1) * K + kt + q1 * 4);
            nb0 = *(const float4*)(Bw + (size_t)(bn + r0) * K + kt + q0 * 4);
            nb1 = *(const float4*)(Bw + (size_t)(bn + r1) * K + kt + q1 * 4);
        }

        #pragma unroll
        for (int k = 0; k < 16; k++) {
            ulonglong2 a01 = *(const ulonglong2*)&As[k * 130 + ty * 8 + 0];
            ulonglong2 a23 = *(const ulonglong2*)&As[k * 130 + ty * 8 + 2];
            ulonglong2 a45 = *(const ulonglong2*)&As[k * 130 + ty * 8 + 4];
            ulonglong2 a67 = *(const ulonglong2*)&As[k * 130 + ty * 8 + 6];
            ulonglong2 b03 = *(const ulonglong2*)&Bs[k * 132 + tx * 8 + 0];
            ulonglong2 b47 = *(const ulonglong2*)&Bs[k * 132 + tx * 8 + 4];
            ull ad[8] = {a01.x, a01.y, a23.x, a23.y, a45.x, a45.y, a67.x, a67.y};
            ull bp[4] = {b03.x, b03.y, b47.x, b47.y};
            #pragma unroll
            for (int i = 0; i < 8; i++)
                #pragma unroll
                for (int j = 0; j < 4; j++)
                    acc[i][j] = ffma2(ad[i], bp[j], acc[i][j]);
        }

        if (it < 31) {
            ull* Asn = Asb + (cur ^ 1) * GA_ULL;
            float* Bsn = Bsb + (cur ^ 1) * GB_F;
            Asn[(q0 * 4 + 0) * 130 + r0] = dup_f(na0.x);
            Asn[(q0 * 4 + 1) * 130 + r0] = dup_f(na0.y);
            Asn[(q0 * 4 + 2) * 130 + r0] = dup_f(na0.z);
            Asn[(q0 * 4 + 3) * 130 + r0] = dup_f(na0.w);
            Asn[(q1 * 4 + 0) * 130 + r1] = dup_f(na1.x);
            Asn[(q1 * 4 + 1) * 130 + r1] = dup_f(na1.y);
            Asn[(q1 * 4 + 2) * 130 + r1] = dup_f(na1.z);
            Asn[(q1 * 4 + 3) * 130 + r1] = dup_f(na1.w);
            Bsn[(q0 * 4 + 0) * 132 + r0] = nb0.x;
            Bsn[(q0 * 4 + 1) * 132 + r0] = nb0.y;
            Bsn[(q0 * 4 + 2) * 132 + r0] = nb0.z;
            Bsn[(q0 * 4 + 3) * 132 + r0] = nb0.w;
            Bsn[(q1 * 4 + 0) * 132 + r1] = nb1.x;
            Bsn[(q1 * 4 + 1) * 132 + r1] = nb1.y;
            Bsn[(q1 * 4 + 2) * 132 + r1] = nb1.z;
            Bsn[(q1 * 4 + 3) * 132 + r1] = nb1.w;
        }
        __syncthreads();
    }

    float4 bx0 = *(const float4*)(bx + bn + tx * 8);
    float4 bx1 = *(const float4*)(bx + bn + tx * 8 + 4);
    #pragma unroll
    for (int i = 0; i < 8; i++) {
        float4 o0, o1;
        o0.x = lo_f(acc[i][0]) + bx0.x;
        o0.y = hi_f(acc[i][0]) + bx0.y;
        o0.z = lo_f(acc[i][1]) + bx0.z;
        o0.w = hi_f(acc[i][1]) + bx0.w;
        o1.x = lo_f(acc[i][2]) + bx1.x;
        o1.y = hi_f(acc[i][2]) + bx1.y;
        o1.z = lo_f(acc[i][3]) + bx1.z;
        o1.w = hi_f(acc[i][3]) + bx1.w;
        float* cp = C + (size_t)(bm + ty * 8 + i) * N + bn + tx * 8;
        *(float4*)(cp)     = o0;
        *(float4*)(cp + 4) = o1;
    }
}

// ============================================================
// Recurrent scan (R12 structure; publish gated by a 512-thread
// named barrier instead of a second full-CTA barrier).
// ============================================================
#define HS_FLOATS  (16 * 1024)
#define RED_FLOATS (16 * 32 * 33)
#define SMEM_BYTES ((HS_FLOATS + RED_FLOATS) * 4)

__global__ __launch_bounds__(NTHREADS, 1) void rnn_scan(
    float* __restrict__ hidden,      // [B, T, H] holds xp, overwritten with h
    const float* __restrict__ Wh,    // [H, H]
    const float* __restrict__ bh,    // [H]
    float* __restrict__ lasth)       // [B, H]
{
    extern __shared__ float smem[];
    float* h_s   = smem;               // [16][1024]
    float* red_s = smem + HS_FLOATS;   // [bi][col][warp] pad 33

    const int tid = threadIdx.x;
    const int l = tid & 31;
    const int w = tid >> 5;            // warp 0..31
    const int cp = l & 15;             // col-pair index
    const int kh = l >> 4;             // 0/1
    const int kq = 2 * w + kh;         // 0..63
    const int gb = blockIdx.x & 3;
    const int cg = blockIdx.x >> 2;
    const int b0 = gb * 16;
    const int c0 = cg * 32 + 2 * cp;

    // Persistent packed weights: 2 cols x 8 k-pairs = 16 ull (32 regs)
    ull wp0[8], wp1[8];
    {
        const ulonglong2* s0 = (const ulonglong2*)(Wh + (size_t)c0 * HDIM + kq * 16);
        const ulonglong2* s1 = (const ulonglong2*)(Wh + (size_t)(c0 + 1) * HDIM + kq * 16);
        #pragma unroll
        for (int q = 0; q < 4; q++) {
            ulonglong2 v = s0[q];
            wp0[2 * q + 0] = v.x;
            wp0[2 * q + 1] = v.y;
            ulonglong2 u = s1[q];
            wp1[2 * q + 0] = u.x;
            wp1[2 * q + 1] = u.y;
        }
    }

    const int colsel = 2 * cp + kh;

    // Epilogue mapping (threads 0..511 only)
    const int bi_e = (tid >> 5) & 15;
    const int col_e = tid & 31;
    const int b_e = b0 + bi_e;
    const int h_e = cg * 32 + col_e;
    const float bh_r = bh[h_e];

    const float* hk = h_s + kq * 16;

    for (int t = 0; t < TSTEPS; t++) {
        // ---- xp prefetch (own slot; independent of h_prev) ----
        size_t oidx = 0;
        float xp_val = 0.0f;
        if (tid < 512) {
            oidx = ((size_t)b_e * TSTEPS + t) * HDIM + h_e;
            xp_val = __ldg(hidden + oidx);
        }

        // ---- wait for all 32 col-CTAs of this group ----
        if (t > 0 && tid == 0) {
            const unsigned target = 32u * (unsigned)t;
            while (ld_acq(&g_flag[FLAG_IDX(gb)]) < target) { }
        }
        __syncthreads();

        // ---- stage h_prev from dense exchange buffer (64KB stream) ----
        {
            const float* base = &g_hx[t & 1][b0][0];    // 16 contiguous rows
            #pragma unroll
            for (int i = 0; i < 4; i++) {
                int idx = tid + NTHREADS * i;           // 0..4095 float4 slots
                float4 v = __ldcg((const float4*)(base + idx * 4));
                *(float4*)(h_s + idx * 4) = v;
            }
        }
        __syncthreads();

        // ---- 16 batches x (2 cols x 16 k); reduce-and-store per bi ----
        #pragma unroll 4
        for (int bi = 0; bi < 16; bi++) {
            const ulonglong2* hp = (const ulonglong2*)(hk + bi * 1024);
            ulonglong2 u0 = hp[0];
            ulonglong2 u1 = hp[1];
            ull a0  = ffma2(u0.x, wp0[0], 0ull);
            ull a1  = ffma2(u0.x, wp1[0], 0ull);
            ull a0b = ffma2(u0.y, wp0[1], 0ull);
            ull a1b = ffma2(u0.y, wp1[1], 0ull);
            a0  = ffma2(u1.x, wp0[2], a0);
            a1  = ffma2(u1.x, wp1[2], a1);
            a0b = ffma2(u1.y, wp0[3], a0b);
            a1b = ffma2(u1.y, wp1[3], a1b);
            ulonglong2 u2 = hp[2];
            ulonglong2 u3 = hp[3];
            a0  = ffma2(u2.x, wp0[4], a0);
            a1  = ffma2(u2.x, wp1[4], a1);
            a0b = ffma2(u2.y, wp0[5], a0b);
            a1b = ffma2(u2.y, wp1[5], a1b);
            a0  = ffma2(u3.x, wp0[6], a0);
            a1  = ffma2(u3.x, wp1[6], a1);
            a0b = ffma2(u3.y, wp0[7], a0b);
            a1b = ffma2(u3.y, wp1[7], a1b);
            float s0 = (lo_f(a0) + hi_f(a0)) + (lo_f(a0b) + hi_f(a0b));
            float s1 = (lo_f(a1) + hi_f(a1)) + (lo_f(a1b) + hi_f(a1b));
            s0 += __shfl_xor_sync(0xffffffffu, s0, 16);
            s1 += __shfl_xor_sync(0xffffffffu, s1, 16);
            red_s[(bi * 32 + colsel) * 33 + w] = (l < 16) ? s0 : s1;
        }
        __syncthreads();

        // ---- final reduce (dual chain) + epilogue (threads 0..511) ----
        if (tid < 512) {
            const float* rp = red_s + (bi_e * 32 + col_e) * 33;
            float sa = 0.0f, sb = 0.0f;
            #pragma unroll
            for (int ww = 0; ww < 16; ww++) {
                sa += rp[ww];
                sb += rp[ww + 16];
            }
            const float val = tanhf(xp_val + sa + sb + bh_r);
            g_hx[(t + 1) & 1][b_e][h_e] = val;          // exchange write first
            hidden[oidx] = val;                          // output record
            if (t == TSTEPS - 1)
                lasth[(size_t)b_e * HDIM + h_e] = val;

            // reducers-only barrier: all 512 epilogue writes done -> publish
            asm volatile("bar.sync 1, 512;" ::: "memory");
            if (tid == 0) red_rel_add1(&g_flag[FLAG_IDX(gb)]);
        }
        // no full-CTA barrier here: the top-of-loop full bar (after the
        // tid0 flag wait, which includes our own publish) orders everything.
    }
}

// ============================================================
// Launch
// ============================================================
extern "C" void kernel_launch(void* const* d_in, const int* in_sizes, int n_in,
                              void* d_out, int out_size) {
    const float* emb = (const float*)d_in[0];   // [B,T,I]
    const float* h0  = (const float*)d_in[1];   // [B,H]
    const float* Wx  = (const float*)d_in[2];   // [H,I]
    const float* bx  = (const float*)d_in[3];   // [H]
    const float* Wh  = (const float*)d_in[4];   // [H,H]
    const float* bh  = (const float*)d_in[5];   // [H]

    float* hidden = (float*)d_out;                            // [B,T,H]
    float* lasth  = hidden + (size_t)BDIM * TSTEPS * HDIM;    // [B,H]

    cudaFuncSetAttribute(rnn_scan, cudaFuncAttributeMaxDynamicSharedMemorySize,
                         SMEM_BYTES);
    cudaFuncSetAttribute(gemm_xproj, cudaFuncAttributeMaxDynamicSharedMemorySize,
                         GSMEM_BYTES);

    // h0 -> exchange buffer, reset flags
    init_h0<<<64, 256>>>(h0);

    // xp = emb @ Wx^T + bx (double-buffered)
    dim3 g1(HDIM / 128, (BDIM * TSTEPS) / 128);
    gemm_xproj<<<g1, 256, GSMEM_BYTES>>>(emb, Wx, bx, hidden);

    // dataflow-synced persistent scan
    rnn_scan<<<NCTAS, NTHREADS, SMEM_BYTES>>>(hidden, Wh, bh, lasth);
}

// round 14
// speedup vs baseline: 1.0135x; 1.0135x over previous
#include <cuda_runtime.h>
#include <cuda_bf16.h>
#include <math.h>

// Problem constants
#define BDIM 64
#define TSTEPS 512
#define IDIM 512
#define HDIM 1024

#define NCTAS 128
#define NTHREADS 1024

typedef unsigned long long ull;

// ---------- packed f32x2 helpers ----------
__device__ __forceinline__ ull ffma2(ull a, ull b, ull c) {
    ull d;
    asm("fma.rn.f32x2 %0, %1, %2, %3;" : "=l"(d) : "l"(a), "l"(b), "l"(c));
    return d;
}
__device__ __forceinline__ float lo_f(ull v) {
    return __uint_as_float((unsigned)(v & 0xffffffffull));
}
__device__ __forceinline__ float hi_f(ull v) {
    return __uint_as_float((unsigned)(v >> 32));
}
__device__ __forceinline__ ull dup_f(float x) {
    unsigned u = __float_as_uint(x);
    return ((ull)u << 32) | u;
}
__device__ __forceinline__ unsigned ld_acq(const unsigned* p) {
    unsigned v;
    asm volatile("ld.acquire.gpu.global.u32 %0, [%1];" : "=r"(v) : "l"(p) : "memory");
    return v;
}
__device__ __forceinline__ void red_rel_add1(unsigned* p) {
    asm volatile("red.release.gpu.global.add.u32 [%0], 1;" :: "l"(p) : "memory");
}

// One flag per batch-group, each in its own 128B sector
__device__ unsigned g_flag[4 * 32];
#define FLAG_IDX(gb) ((gb) * 32)

// Contiguous fp32 ping-pong h-exchange buffer
__device__ __align__(16) float g_hx[2][BDIM][HDIM];

// init: h0 -> g_hx[0]; reset flags
__global__ void init_h0(const float* __restrict__ h0) {
    if (blockIdx.x == 0 && threadIdx.x < 4) g_flag[threadIdx.x * 32] = 0u;
    int idx = blockIdx.x * 256 + threadIdx.x;       // 16384 float4 slots
    float4 v = *(const float4*)(h0 + (size_t)idx * 4);
    int b = idx >> 8, g = idx & 255;
    *(float4*)(&g_hx[0][b][g * 4]) = v;
}

// ============================================================
// Kernel 1: xp = embeddings @ Wx^T + bx  -> written into hidden
// NT gemm, BM=128 BN=128 BK=16, 512 threads, 8x4/thread, FFMA2.
// acc = 16 ull (32 regs) -> <=64 regs -> 2 CTAs/SM = 8 warps/SMSP.
// A smem dup-packed; whole warp shares ty -> A reads are 1-phase
// broadcasts. B read as natural col-pairs (1 LDS.128).
// ============================================================
__global__ __launch_bounds__(512, 2) void gemm_xproj(
    const float* __restrict__ A,
    const float* __restrict__ Bw,
    const float* __restrict__ bx,
    float* __restrict__ C)
{
    __shared__ __align__(16) ull   As_d[16][130];   // dup-packed (a,a)
    __shared__ __align__(16) float Bs[16][132];

    const int K = IDIM;
    const int N = HDIM;
    const int bm = blockIdx.y * 128;
    const int bn = blockIdx.x * 128;
    const int tid = threadIdx.x;
    const int tx = tid & 31;          // 4 cols: bn + tx*4 ..
    const int ty = tid >> 5;          // 8 rows: bm + ty*8 ..

    // one float4 load job per thread per operand per tile
    const int lr = tid >> 2;          // 0..127
    const int lq = tid & 3;           // 0..3

    ull acc[8][2];                    // [row][colpair]
    #pragma unroll
    for (int i = 0; i < 8; i++) {
        acc[i][0] = 0ull;
        acc[i][1] = 0ull;
    }

    for (int kt = 0; kt < K; kt += 16) {
        {
            float4 va = *(const float4*)(A  + (size_t)(bm + lr) * K + kt + lq * 4);
            float4 vb = *(const float4*)(Bw + (size_t)(bn + lr) * K + kt + lq * 4);
            As_d[lq * 4 + 0][lr] = dup_f(va.x);
            As_d[lq * 4 + 1][lr] = dup_f(va.y);
            As_d[lq * 4 + 2][lr] = dup_f(va.z);
            As_d[lq * 4 + 3][lr] = dup_f(va.w);
            Bs[lq * 4 + 0][lr] = vb.x;
            Bs[lq * 4 + 1][lr] = vb.y;
            Bs[lq * 4 + 2][lr] = vb.z;
            Bs[lq * 4 + 3][lr] = vb.w;
        }
        __syncthreads();

        #pragma unroll
        for (int k = 0; k < 16; k++) {
            ulonglong2 a01 = *(const ulonglong2*)&As_d[k][ty * 8 + 0];
            ulonglong2 a23 = *(const ulonglong2*)&As_d[k][ty * 8 + 2];
            ulonglong2 a45 = *(const ulonglong2*)&As_d[k][ty * 8 + 4];
            ulonglong2 a67 = *(const ulonglong2*)&As_d[k][ty * 8 + 6];
            ulonglong2 bq  = *(const ulonglong2*)&Bs[k][tx * 4];
            ull ad[8] = {a01.x, a01.y, a23.x, a23.y, a45.x, a45.y, a67.x, a67.y};
            #pragma unroll
            for (int i = 0; i < 8; i++) {
                acc[i][0] = ffma2(ad[i], bq.x, acc[i][0]);
                acc[i][1] = ffma2(ad[i], bq.y, acc[i][1]);
            }
        }
        __syncthreads();
    }

    float4 bxv = *(const float4*)(bx + bn + tx * 4);
    #pragma unroll
    for (int i = 0; i < 8; i++) {
        float4 o;
        o.x = lo_f(acc[i][0]) + bxv.x;
        o.y = hi_f(acc[i][0]) + bxv.y;
        o.z = lo_f(acc[i][1]) + bxv.z;
        o.w = hi_f(acc[i][1]) + bxv.w;
        *(float4*)(C + (size_t)(bm + ty * 8 + i) * N + bn + tx * 4) = o;
    }
}

// ============================================================
// Recurrent scan (exact R12 structure — the 4019us config).
// 128 CTAs x 1024 threads. CTA = (gb: 16 batches) x (cg: 32 H cols).
// Thread (w, l): cols {cg*32 + 2*(l&15), +1}; kq = 2w + (l>>4),
// k in [16kq, 16kq+16). Weights 16 ull = 32 regs, persistent.
// h exchanged via contiguous fp32 ping-pong g_hx.
// ============================================================
#define HS_FLOATS  (16 * 1024)
#define RED_FLOATS (16 * 32 * 33)
#define SMEM_BYTES ((HS_FLOATS + RED_FLOATS) * 4)

__global__ __launch_bounds__(NTHREADS, 1) void rnn_scan(
    float* __restrict__ hidden,      // [B, T, H] holds xp, overwritten with h
    const float* __restrict__ Wh,    // [H, H]
    const float* __restrict__ bh,    // [H]
    float* __restrict__ lasth)       // [B, H]
{
    extern __shared__ float smem[];
    float* h_s   = smem;               // [16][1024]
    float* red_s = smem + HS_FLOATS;   // [bi][col][warp] pad 33

    const int tid = threadIdx.x;
    const int l = tid & 31;
    const int w = tid >> 5;            // warp 0..31
    const int cp = l & 15;             // col-pair index
    const int kh = l >> 4;             // 0/1
    const int kq = 2 * w + kh;         // 0..63
    const int gb = blockIdx.x & 3;
    const int cg = blockIdx.x >> 2;
    const int b0 = gb * 16;
    const int c0 = cg * 32 + 2 * cp;

    // Persistent packed weights: 2 cols x 8 k-pairs = 16 ull (32 regs)
    ull wp0[8], wp1[8];
    {
        const ulonglong2* s0 = (const ulonglong2*)(Wh + (size_t)c0 * HDIM + kq * 16);
        const ulonglong2* s1 = (const ulonglong2*)(Wh + (size_t)(c0 + 1) * HDIM + kq * 16);
        #pragma unroll
        for (int q = 0; q < 4; q++) {
            ulonglong2 v = s0[q];
            wp0[2 * q + 0] = v.x;
            wp0[2 * q + 1] = v.y;
            ulonglong2 u = s1[q];
            wp1[2 * q + 0] = u.x;
            wp1[2 * q + 1] = u.y;
        }
    }

    const int colsel = 2 * cp + kh;

    // Epilogue mapping (threads 0..511 only)
    const int bi_e = (tid >> 5) & 15;
    const int col_e = tid & 31;
    const int b_e = b0 + bi_e;
    const int h_e = cg * 32 + col_e;
    const float bh_r = bh[h_e];

    const float* hk = h_s + kq * 16;

    for (int t = 0; t < TSTEPS; t++) {
        // ---- xp prefetch (own slot; independent of h_prev) ----
        size_t oidx = 0;
        float xp_val = 0.0f;
        if (tid < 512) {
            oidx = ((size_t)b_e * TSTEPS + t) * HDIM + h_e;
            xp_val = __ldg(hidden + oidx);
        }

        // ---- wait for all 32 col-CTAs of this group ----
        if (t > 0 && tid == 0) {
            const unsigned target = 32u * (unsigned)t;
            while (ld_acq(&g_flag[FLAG_IDX(gb)]) < target) { }
        }
        __syncthreads();

        // ---- stage h_prev from dense exchange buffer (64KB stream) ----
        {
            const float* base = &g_hx[t & 1][b0][0];    // 16 contiguous rows
            #pragma unroll
            for (int i = 0; i < 4; i++) {
                int idx = tid + NTHREADS * i;           // 0..4095 float4 slots
                float4 v = __ldcg((const float4*)(base + idx * 4));
                *(float4*)(h_s + idx * 4) = v;
            }
        }
        __syncthreads();

        // ---- 16 batches x (2 cols x 16 k); reduce-and-store per bi ----
        #pragma unroll 4
        for (int bi = 0; bi < 16; bi++) {
            const ulonglong2* hp = (const ulonglong2*)(hk + bi * 1024);
            ulonglong2 u0 = hp[0];
            ulonglong2 u1 = hp[1];
            ull a0  = ffma2(u0.x, wp0[0], 0ull);
            ull a1  = ffma2(u0.x, wp1[0], 0ull);
            ull a0b = ffma2(u0.y, wp0[1], 0ull);
            ull a1b = ffma2(u0.y, wp1[1], 0ull);
            a0  = ffma2(u1.x, wp0[2], a0);
            a1  = ffma2(u1.x, wp1[2], a1);
            a0b = ffma2(u1.y, wp0[3], a0b);
            a1b = ffma2(u1.y, wp1[3], a1b);
            ulonglong2 u2 = hp[2];
            ulonglong2 u3 = hp[3];
            a0  = ffma2(u2.x, wp0[4], a0);
            a1  = ffma2(u2.x, wp1[4], a1);
            a0b = ffma2(u2.y, wp0[5], a0b);
            a1b = ffma2(u2.y, wp1[5], a1b);
            a0  = ffma2(u3.x, wp0[6], a0);
            a1  = ffma2(u3.x, wp1[6], a1);
            a0b = ffma2(u3.y, wp0[7], a0b);
            a1b = ffma2(u3.y, wp1[7], a1b);
            float s0 = (lo_f(a0) + hi_f(a0)) + (lo_f(a0b) + hi_f(a0b));
            float s1 = (lo_f(a1) + hi_f(a1)) + (lo_f(a1b) + hi_f(a1b));
            s0 += __shfl_xor_sync(0xffffffffu, s0, 16);
            s1 += __shfl_xor_sync(0xffffffffu, s1, 16);
            red_s[(bi * 32 + colsel) * 33 + w] = (l < 16) ? s0 : s1;
        }
        __syncthreads();

        // ---- final reduce (dual chain) + epilogue (threads 0..511) ----
        if (tid < 512) {
            const float* rp = red_s + (bi_e * 32 + col_e) * 33;
            float sa = 0.0f, sb = 0.0f;
            #pragma unroll
            for (int ww = 0; ww < 16; ww++) {
                sa += rp[ww];
                sb += rp[ww + 16];
            }
            const float val = tanhf(xp_val + sa + sb + bh_r);
            g_hx[(t + 1) & 1][b_e][h_e] = val;          // exchange write first
            hidden[oidx] = val;                          // output record
            if (t == TSTEPS - 1)
                lasth[(size_t)b_e * HDIM + h_e] = val;
        }

        // ---- publish ----
        __syncthreads();
        if (tid == 0) red_rel_add1(&g_flag[FLAG_IDX(gb)]);
    }
}

// ============================================================
// Launch
// ============================================================
extern "C" void kernel_launch(void* const* d_in, const int* in_sizes, int n_in,
                              void* d_out, int out_size) {
    const float* emb = (const float*)d_in[0];   // [B,T,I]
    const float* h0  = (const float*)d_in[1];   // [B,H]
    const float* Wx  = (const float*)d_in[2];   // [H,I]
    const float* bx  = (const float*)d_in[3];   // [H]
    const float* Wh  = (const float*)d_in[4];   // [H,H]
    const float* bh  = (const float*)d_in[5];   // [H]

    float* hidden = (float*)d_out;                            // [B,T,H]
    float* lasth  = hidden + (size_t)BDIM * TSTEPS * HDIM;    // [B,H]

    cudaFuncSetAttribute(rnn_scan, cudaFuncAttributeMaxDynamicSharedMemorySize,
                         SMEM_BYTES);

    // h0 -> exchange buffer, reset flags
    init_h0<<<64, 256>>>(h0);

    // xp = emb @ Wx^T + bx (512 threads, 8 warps/SMSP)
    dim3 g1(HDIM / 128, (BDIM * TSTEPS) / 128);
    gemm_xproj<<<g1, 512>>>(emb, Wx, bx, hidden);

    // dataflow-synced persistent scan
    rnn_scan<<<NCTAS, NTHREADS, SMEM_BYTES>>>(hidden, Wh, bh, lasth);
}